// round 10
// baseline (speedup 1.0000x reference)
#include <cuda_runtime.h>
#include <cuda_fp16.h>
#include <math.h>
#include <stdint.h>

// Problem constants
#define T_TOK 1024
#define D_HID 2048
#define NQ 32
#define NKV 8
#define HD 64
#define GQ 4
#define SEQ_LEN 256
#define THETA 500000.0f

#define K2 1024          // Kd/2 in u32 (all GEMMs have Kd = 2048)

// fp32 scratch
__device__ float g_q[T_TOK * NQ * HD];
__device__ float g_k[T_TOK * NKV * HD];
__device__ float g_v[T_TOK * NKV * HD];

// pre-split fp16 (packed pairs as u32), K-major rows
__device__ uint32_t g_xh[T_TOK * K2],  g_xl[T_TOK * K2];   // x hi/lo
__device__ uint32_t g_aoh[T_TOK * K2], g_aol[T_TOK * K2];  // attn out hi/lo
__device__ uint32_t g_wqh[2048 * K2];                      // weights: hi only
__device__ uint32_t g_wkh[512 * K2];
__device__ uint32_t g_wvh[512 * K2];
__device__ uint32_t g_woh[2048 * K2];

__device__ __forceinline__ void split_pack_f16(float f0, float f1,
                                               uint32_t& hp, uint32_t& lp) {
    __half h0 = __float2half_rn(f0);
    __half h1 = __float2half_rn(f1);
    float r0 = f0 - __half2float(h0);
    float r1 = f1 - __half2float(h1);
    __half l0 = __float2half_rn(r0);
    __half l1 = __float2half_rn(r1);
    hp = ((uint32_t)__half_as_ushort(h1) << 16) | (uint32_t)__half_as_ushort(h0);
    lp = ((uint32_t)__half_as_ushort(l1) << 16) | (uint32_t)__half_as_ushort(l0);
}

__device__ __forceinline__ uint32_t pack_f16(float f0, float f1) {
    return ((uint32_t)__half_as_ushort(__float2half_rn(f1)) << 16)
         | (uint32_t)__half_as_ushort(__float2half_rn(f0));
}

// ---------------------------------------------------------------------------
// Split kernels
// ---------------------------------------------------------------------------
__global__ void split_a_kernel(const float* __restrict__ A,
                               uint32_t* __restrict__ Ah, uint32_t* __restrict__ Al,
                               int total2) {
    int i = blockIdx.x * blockDim.x + threadIdx.x;
    if (i >= total2) return;
    float2 f = ((const float2*)A)[i];
    uint32_t h, l;
    split_pack_f16(f.x, f.y, h, l);
    Ah[i] = h; Al[i] = l;
}

// All four weight transposes+fp16 packs in one kernel. Tiles of 32n x 32k.
// ct: 0-63 -> Wq, 64-79 -> Wk, 80-95 -> Wv, 96-159 -> Wo.
__global__ __launch_bounds__(256) void split_w_all_kernel(
    const float* __restrict__ Wq, const float* __restrict__ Wk,
    const float* __restrict__ Wv, const float* __restrict__ Wo) {
    __shared__ float tile[32][33];
    const int ct = blockIdx.x;
    const float* W; uint32_t* Wh; int N, n0;
    if (ct < 64)      { W = Wq; Wh = g_wqh; N = 2048; n0 = ct * 32; }
    else if (ct < 80) { W = Wk; Wh = g_wkh; N = 512;  n0 = (ct - 64) * 32; }
    else if (ct < 96) { W = Wv; Wh = g_wvh; N = 512;  n0 = (ct - 80) * 32; }
    else              { W = Wo; Wh = g_woh; N = 2048; n0 = (ct - 96) * 32; }
    const int k0 = blockIdx.y * 32;
    const int tx = threadIdx.x & 31, ty = threadIdx.x >> 5;
    #pragma unroll
    for (int i = 0; i < 4; i++)
        tile[ty + i * 8][tx] = W[(size_t)(k0 + ty + i * 8) * N + n0 + tx];
    __syncthreads();
    #pragma unroll
    for (int i = 0; i < 2; i++) {
        int task = threadIdx.x + i * 256;
        int n  = task >> 4;
        int kk = task & 15;
        Wh[(size_t)(n0 + n) * K2 + (k0 >> 1) + kk] =
            pack_f16(tile[kk * 2][n], tile[kk * 2 + 1][n]);
    }
}

// ---------------------------------------------------------------------------
// mma.sync fp16x2 GEMM: C = (Ah+Al) * Bh. CTA tile 128x64, BK=64, 2-stage
// cp.async, 8 warps as 4(row) x 2(col), warp tile 32x32. 2 CTAs/SM.
// ---------------------------------------------------------------------------
#define SAK 36                          // u32 row stride (32 data + 4 pad)
#define A_U32 (128 * SAK)               // 4608
#define B_U32 (64 * SAK)                // 2304
#define STAGE_U32 (2 * A_U32 + B_U32)   // Ah, Al, Bh = 11520 u32
#define GEMM_SMEM_BYTES (2 * STAGE_U32 * 4)   // 92160

#define OFF_AL (A_U32)
#define OFF_BH (2 * A_U32)

__device__ __forceinline__ void cp16(uint32_t saddr, const uint32_t* gptr) {
    asm volatile("cp.async.cg.shared.global [%0], [%1], 16;\n" :: "r"(saddr), "l"(gptr));
}
__device__ __forceinline__ void cp_commit() { asm volatile("cp.async.commit_group;\n"); }
__device__ __forceinline__ void cp_wait0()  { asm volatile("cp.async.wait_group 0;\n"); }

__device__ __forceinline__ void ldsm4(uint32_t& r0, uint32_t& r1, uint32_t& r2,
                                      uint32_t& r3, uint32_t addr) {
    asm volatile("ldmatrix.sync.aligned.m8n8.x4.shared.b16 {%0,%1,%2,%3}, [%4];"
                 : "=r"(r0), "=r"(r1), "=r"(r2), "=r"(r3) : "r"(addr));
}

__device__ __forceinline__ void mma16816(float* c, const uint32_t* a,
                                         uint32_t b0, uint32_t b1) {
    asm volatile(
        "mma.sync.aligned.m16n8k16.row.col.f32.f16.f16.f32 "
        "{%0,%1,%2,%3}, {%4,%5,%6,%7}, {%8,%9}, {%0,%1,%2,%3};"
        : "+f"(c[0]), "+f"(c[1]), "+f"(c[2]), "+f"(c[3])
        : "r"(a[0]), "r"(a[1]), "r"(a[2]), "r"(a[3]), "r"(b0), "r"(b1));
}

__device__ __forceinline__ void gemm_core(
    const uint32_t* __restrict__ Ahg, const uint32_t* __restrict__ Alg,
    const uint32_t* __restrict__ Bhg,
    float* __restrict__ C, int Ncols, int brow, int bcol, uint32_t* sm)
{
    const int tid  = threadIdx.x;
    const int wid  = tid >> 5;
    const int lane = tid & 31;
    const int gid  = lane >> 2;
    const int tig  = lane & 3;
    const int wm   = wid & 3;          // 0..3 -> 32 rows each
    const int wn   = wid >> 2;         // 0..1 -> 32 cols each

    uint32_t sbase = (uint32_t)__cvta_generic_to_shared(sm);

    // staging chunk mapping: chunk id c -> row = c>>3, kc = c&7 (16B chunks)
    int arow[4], akc[4]; uint32_t asml[4];
    #pragma unroll
    for (int t = 0; t < 4; t++) {
        int c = tid + t * 256;
        arow[t] = c >> 3; akc[t] = c & 7;
        asml[t] = (arow[t] * SAK + akc[t] * 4) * 4;
    }
    int brw[2], bkc[2]; uint32_t bsml[2];
    #pragma unroll
    for (int t = 0; t < 2; t++) {
        int c = tid + t * 256;
        brw[t] = c >> 3; bkc[t] = c & 7;
        bsml[t] = (brw[t] * SAK + bkc[t] * 4) * 4;
    }

    const uint32_t* gAh[4]; const uint32_t* gAl[4];
    #pragma unroll
    for (int t = 0; t < 4; t++) {
        gAh[t] = Ahg + (size_t)(brow + arow[t]) * K2 + akc[t] * 4;
        gAl[t] = Alg + (size_t)(brow + arow[t]) * K2 + akc[t] * 4;
    }
    const uint32_t* gBh[2];
    #pragma unroll
    for (int t = 0; t < 2; t++)
        gBh[t] = Bhg + (size_t)(bcol + brw[t]) * K2 + bkc[t] * 4;

    float acc[8][4];
    #pragma unroll
    for (int i = 0; i < 8; i++)
        #pragma unroll
        for (int j = 0; j < 4; j++) acc[i][j] = 0.f;

    const int a_r = (lane & 15);
    const int a_c = (lane >> 4) * 4;
    const int b_r = (lane & 7);
    const int b_c = (lane >> 3) * 4;

    const int nK = 2048 / 64;   // 32 k-tiles

    auto stage = [&](int kt, int buf) {
        const int ko = kt * 32;
        const uint32_t sb = sbase + buf * STAGE_U32 * 4;
        #pragma unroll
        for (int t = 0; t < 4; t++) {
            cp16(sb + asml[t],               gAh[t] + ko);
            cp16(sb + OFF_AL * 4 + asml[t],  gAl[t] + ko);
        }
        #pragma unroll
        for (int t = 0; t < 2; t++)
            cp16(sb + OFF_BH * 4 + bsml[t],  gBh[t] + ko);
    };

    stage(0, 0); cp_commit();

    for (int kt = 0; kt < nK; kt++) {
        cp_wait0();
        __syncthreads();
        if (kt + 1 < nK) { stage(kt + 1, (kt + 1) & 1); cp_commit(); }

        const uint32_t stg = sbase + (kt & 1) * STAGE_U32 * 4;
        const uint32_t aAh = stg;
        const uint32_t aAl = stg + OFF_AL * 4;
        const uint32_t aBh = stg + OFF_BH * 4;

        #pragma unroll
        for (int hh2 = 0; hh2 < 2; hh2++) {      // k32 slab
            uint32_t bh[4][4];
            #pragma unroll
            for (int nt = 0; nt < 4; nt++) {
                const uint32_t boff =
                    ((wn * 32 + nt * 8 + b_r) * SAK + hh2 * 16 + b_c) * 4;
                ldsm4(bh[nt][0], bh[nt][1], bh[nt][2], bh[nt][3], aBh + boff);
            }
            #pragma unroll
            for (int h = 0; h < 2; h++) {        // k16 within slab
                uint32_t ah[2][4], al[2][4];
                #pragma unroll
                for (int mt = 0; mt < 2; mt++) {
                    const uint32_t aoff =
                        ((wm * 32 + mt * 16 + a_r) * SAK + (hh2 * 2 + h) * 8 + a_c) * 4;
                    ldsm4(ah[mt][0], ah[mt][1], ah[mt][2], ah[mt][3], aAh + aoff);
                    ldsm4(al[mt][0], al[mt][1], al[mt][2], al[mt][3], aAl + aoff);
                }
                // hi product
                #pragma unroll
                for (int mt = 0; mt < 2; mt++)
                    #pragma unroll
                    for (int nt = 0; nt < 4; nt++)
                        mma16816(acc[mt * 4 + nt], ah[mt],
                                 bh[nt][2 * h], bh[nt][2 * h + 1]);
                // lo product
                #pragma unroll
                for (int mt = 0; mt < 2; mt++)
                    #pragma unroll
                    for (int nt = 0; nt < 4; nt++)
                        mma16816(acc[mt * 4 + nt], al[mt],
                                 bh[nt][2 * h], bh[nt][2 * h + 1]);
            }
        }
    }

    // epilogue
    #pragma unroll
    for (int mt = 0; mt < 2; mt++)
        #pragma unroll
        for (int nt = 0; nt < 4; nt++) {
            const float* c = acc[mt * 4 + nt];
            const int row = brow + wm * 32 + mt * 16 + gid;
            const int col = bcol + wn * 32 + nt * 8 + tig * 2;
            *(float2*)(C + (size_t)row * Ncols + col)       = make_float2(c[0], c[1]);
            *(float2*)(C + (size_t)(row + 8) * Ncols + col) = make_float2(c[2], c[3]);
        }
}

// QKV fused: 48 col tiles of 64: 0-31 -> Q, 32-39 -> K, 40-47 -> V
__global__ __launch_bounds__(256, 2) void qkv_gemm_kernel() {
    extern __shared__ uint32_t sm[];
    const int ct = blockIdx.x;
    const uint32_t* Bh; float* C; int Ncols, colt;
    if (ct < 32)      { Bh = g_wqh; C = g_q; Ncols = NQ * HD;  colt = ct; }
    else if (ct < 40) { Bh = g_wkh; C = g_k; Ncols = NKV * HD; colt = ct - 32; }
    else              { Bh = g_wvh; C = g_v; Ncols = NKV * HD; colt = ct - 40; }
    gemm_core(g_xh, g_xl, Bh, C, Ncols, blockIdx.y * 128, colt * 64, sm);
}

__global__ __launch_bounds__(256, 2) void out_gemm_kernel(float* __restrict__ out) {
    extern __shared__ uint32_t sm[];
    gemm_core(g_aoh, g_aol, g_woh, out, D_HID,
              blockIdx.y * 128, blockIdx.x * 64, sm);
}

// ---------------------------------------------------------------------------
// RoPE in-place on q and k (exp2f instead of powf)
// ---------------------------------------------------------------------------
__global__ void rope_kernel(const int* __restrict__ positions) {
    const int half = HD / 2;
    int idx = blockIdx.x * blockDim.x + threadIdx.x;
    const int total = T_TOK * (NQ + NKV) * half;
    if (idx >= total) return;

    int i    = idx % half;
    int head = (idx / half) % (NQ + NKV);
    int t    = idx / (half * (NQ + NKV));

    // THETA^(-i/32) = 2^(-i * log2(THETA)/32); log2(500000) = 18.9315685693
    float inv_freq = exp2f(-(float)i * (18.9315685693f / 32.f));
    float f = (float)positions[t] * inv_freq;
    float s, c;
    sincosf(f, &s, &c);

    float* base;
    if (head < NQ) base = g_q + ((size_t)t * NQ + head) * HD;
    else           base = g_k + ((size_t)t * NKV + (head - NQ)) * HD;

    float x1 = base[i];
    float x2 = base[i + half];
    base[i]        = x1 * c - x2 * s;
    base[i + half] = x2 * c + x1 * s;
}

// ---------------------------------------------------------------------------
// Attention: block = (32-token q-tile, kv-head), 512 threads.
// Thread = (row = qi + 32*g, quarter of head-dim). 256 blocks total.
// Epilogue writes fp16 hi/lo split directly.
// ---------------------------------------------------------------------------
#define KVST 68

__global__ __launch_bounds__(512) void attn_kernel() {
    const int tid = threadIdx.x;
    const int row = tid >> 2;            // 0..127 = qi + 32*g
    const int qr  = tid & 3;             // quarter of head-dim
    const int qi  = row & 31;
    const int g   = row >> 5;
    const int kh  = blockIdx.y;
    const int seq = blockIdx.x >> 3;
    const int qt  = blockIdx.x & 7;      // 8 q-tiles of 32 per sequence
    const int t   = seq * SEQ_LEN + qt * 32 + qi;
    const int h0  = qr * 16;

    __shared__ float sk[32 * KVST];
    __shared__ float sv[32 * KVST];

    float4 q4[4];
    {
        const float* qp = g_q + ((size_t)t * NQ + kh * GQ + g) * HD + h0;
        #pragma unroll
        for (int i = 0; i < 4; i++) q4[i] = *(const float4*)(qp + i * 4);
    }

    float4 acc4[4];
    #pragma unroll
    for (int i = 0; i < 4; i++) acc4[i] = make_float4(0.f, 0.f, 0.f, 0.f);
    float l = 0.f;

    const int srow = tid >> 4;           // staging: 32 rows x 16 chunks
    const int sc4  = (tid & 15) * 4;

    for (int c = 0; c <= qt; c++) {
        const int base = seq * SEQ_LEN + c * 32;
        if (c) __syncthreads();
        *(float4*)(sk + srow * KVST + sc4) =
            *(const float4*)(g_k + ((size_t)(base + srow) * NKV + kh) * HD + sc4);
        *(float4*)(sv + srow * KVST + sc4) =
            *(const float4*)(g_v + ((size_t)(base + srow) * NKV + kh) * HD + sc4);
        __syncthreads();

        const int jmax = (c == qt) ? qi : 31;
        for (int jj = 0; jj < 32; jj++) {
            const float4* kr = (const float4*)(sk + jj * KVST + h0);
            float d0 = 0.f, d1 = 0.f;
            {
                float4 k0 = kr[0], k1 = kr[1], k2 = kr[2], k3 = kr[3];
                d0 = fmaf(k0.x, q4[0].x, d0); d1 = fmaf(k0.y, q4[0].y, d1);
                d0 = fmaf(k0.z, q4[0].z, d0); d1 = fmaf(k0.w, q4[0].w, d1);
                d0 = fmaf(k1.x, q4[1].x, d0); d1 = fmaf(k1.y, q4[1].y, d1);
                d0 = fmaf(k1.z, q4[1].z, d0); d1 = fmaf(k1.w, q4[1].w, d1);
                d0 = fmaf(k2.x, q4[2].x, d0); d1 = fmaf(k2.y, q4[2].y, d1);
                d0 = fmaf(k2.z, q4[2].z, d0); d1 = fmaf(k2.w, q4[2].w, d1);
                d0 = fmaf(k3.x, q4[3].x, d0); d1 = fmaf(k3.y, q4[3].y, d1);
                d0 = fmaf(k3.z, q4[3].z, d0); d1 = fmaf(k3.w, q4[3].w, d1);
            }
            float d = d0 + d1;
            d += __shfl_xor_sync(0xffffffffu, d, 1);
            d += __shfl_xor_sync(0xffffffffu, d, 2);
            float p = (jj <= jmax) ? __expf(d * 0.125f) : 0.f;
            l += p;
            const float4* vr = (const float4*)(sv + jj * KVST + h0);
            #pragma unroll
            for (int i = 0; i < 4; i++) {
                float4 vv = vr[i];
                acc4[i].x = fmaf(p, vv.x, acc4[i].x);
                acc4[i].y = fmaf(p, vv.y, acc4[i].y);
                acc4[i].z = fmaf(p, vv.z, acc4[i].z);
                acc4[i].w = fmaf(p, vv.w, acc4[i].w);
            }
        }
    }

    const float inv = 1.0f / l;
    const size_t u32base = (size_t)t * 1024 + (kh * GQ + g) * 32 + qr * 8;
    #pragma unroll
    for (int i = 0; i < 4; i++) {
        float o0 = acc4[i].x * inv, o1 = acc4[i].y * inv;
        float o2 = acc4[i].z * inv, o3 = acc4[i].w * inv;
        uint32_t h01, l01, h23, l23;
        split_pack_f16(o0, o1, h01, l01);
        split_pack_f16(o2, o3, h23, l23);
        g_aoh[u32base + i * 2]     = h01;
        g_aoh[u32base + i * 2 + 1] = h23;
        g_aol[u32base + i * 2]     = l01;
        g_aol[u32base + i * 2 + 1] = l23;
    }
}

// ---------------------------------------------------------------------------
extern "C" void kernel_launch(void* const* d_in, const int* in_sizes, int n_in,
                              void* d_out, int out_size) {
    const float* x  = (const float*)d_in[0];
    const float* Wq = (const float*)d_in[1];
    const float* Wk = (const float*)d_in[2];
    const float* Wv = (const float*)d_in[3];
    const float* Wo = (const float*)d_in[4];
    const int* positions = (const int*)d_in[5];
    float* out = (float*)d_out;

    static bool attr_done = false;
    if (!attr_done) {
        cudaFuncSetAttribute(qkv_gemm_kernel,
                             cudaFuncAttributeMaxDynamicSharedMemorySize, GEMM_SMEM_BYTES);
        cudaFuncSetAttribute(out_gemm_kernel,
                             cudaFuncAttributeMaxDynamicSharedMemorySize, GEMM_SMEM_BYTES);
        attr_done = true;
    }

    uint32_t *xh, *xl;
    cudaGetSymbolAddress((void**)&xh, g_xh);
    cudaGetSymbolAddress((void**)&xl, g_xl);

    // Pre-split input and all weights
    split_a_kernel<<<(T_TOK * K2 + 255) / 256, 256>>>(x, xh, xl, T_TOK * K2);
    split_w_all_kernel<<<dim3(160, 64), 256>>>(Wq, Wk, Wv, Wo);

    // QKV projections
    qkv_gemm_kernel<<<dim3(48, T_TOK / 128), 256, GEMM_SMEM_BYTES>>>();

    // RoPE
    {
        int total = T_TOK * (NQ + NKV) * (HD / 2);
        rope_kernel<<<(total + 255) / 256, 256>>>(positions);
    }

    // Attention (writes split ao directly)
    attn_kernel<<<dim3(32, NKV), 512>>>();

    // Output projection
    out_gemm_kernel<<<dim3(D_HID / 64, T_TOK / 128), 256, GEMM_SMEM_BYTES>>>(out);
}